// round 2
// baseline (speedup 1.0000x reference)
#include <cuda_runtime.h>
#include <cstdint>
#include <cstddef>

#define N_SRC   100000
#define N_OUT   100000
#define N_EDGES 1600000
#define C       128

// ---------------- scratch (device globals; no allocation allowed) ------------
__device__ float g_Wx[(size_t)N_SRC * C];    // node-major: Wx[n][o], 51.2 MB
__device__ float g_expa[N_SRC];
__device__ int   g_cnt[N_OUT];
__device__ int   g_off[N_OUT + 1];
__device__ int   g_cur[N_OUT];
__device__ int   g_srcs[N_EDGES];

// ---------------- kernel 1: zero counters ------------------------------------
__global__ void zero_cnt_kernel()
{
    int i = blockIdx.x * blockDim.x + threadIdx.x;
    if (i < N_OUT) g_cnt[i] = 0;
}

// ---------------- kernel 2: histogram of targets -----------------------------
__global__ __launch_bounds__(256) void hist_kernel(const int* __restrict__ edges)
{
    int e      = blockIdx.x * blockDim.x + threadIdx.x;
    int stride = gridDim.x * blockDim.x;
    for (; e < N_EDGES; e += stride) {
        const int tgt = reinterpret_cast<const int2*>(edges)[e].x;
        atomicAdd(&g_cnt[tgt], 1);
    }
}

// ---------------- kernel 3: exclusive scan (single block) --------------------
__global__ __launch_bounds__(1024) void scan_kernel()
{
    __shared__ int sums[1024];
    const int T  = 1024;
    const int CH = (N_OUT + T - 1) / T;   // 98
    const int t  = threadIdx.x;
    const int beg = t * CH;
    const int end = (beg + CH < N_OUT) ? beg + CH : N_OUT;

    int mysum = 0;
    for (int i = beg; i < end; i++) mysum += g_cnt[i];
    sums[t] = mysum;
    __syncthreads();

    // inclusive Hillis-Steele scan
    for (int o = 1; o < T; o <<= 1) {
        int v = (t >= o) ? sums[t - o] : 0;
        __syncthreads();
        sums[t] += v;
        __syncthreads();
    }

    int running = sums[t] - mysum;   // exclusive base for this chunk
    for (int i = beg; i < end; i++) {
        g_off[i] = running;
        g_cur[i] = running;
        running += g_cnt[i];
    }
    if (t == T - 1) g_off[N_OUT] = sums[T - 1];
}

// ---------------- kernel 4: reorder edges into CSR buckets -------------------
__global__ __launch_bounds__(256) void reorder_kernel(const int* __restrict__ edges)
{
    int e      = blockIdx.x * blockDim.x + threadIdx.x;
    int stride = gridDim.x * blockDim.x;
    for (; e < N_EDGES; e += stride) {
        const int2 ts = reinterpret_cast<const int2*>(edges)[e];
        const int pos = atomicAdd(&g_cur[ts.x], 1);
        g_srcs[pos] = ts.y;
    }
}

// ---------------- kernel 5: Wx = W @ x + b, fused score epilogue -------------
__global__ __launch_bounds__(256) void gemm_kernel(
    const float* __restrict__ x,      // (C, N_SRC)
    const float* __restrict__ W,      // (C_OUT, C_IN) row-major
    const float* __restrict__ b,      // (C,)
    const float* __restrict__ att,    // (C,)
    const float* __restrict__ alphap) // scalar
{
    __shared__ float xs[16][132];   // xs[k][n]
    __shared__ float ws[16][132];   // ws[k][o]
    __shared__ float bs[128];
    __shared__ float ats[128];
    __shared__ float sdot[128];

    const int tid   = threadIdx.x;
    const int nbase = blockIdx.x * 128;

    if (tid < 128) {
        bs[tid]   = b[tid];
        ats[tid]  = att[tid];
        sdot[tid] = 0.f;
    }

    const int tn = tid >> 4;        // 0..15 node group
    const int to = tid & 15;        // 0..15 out group

    const int lc = tid >> 4;          // xs row (k) 0..15
    const int ln = (tid & 15) * 8;    // xs col (n)
    const int wo = tid >> 1;          // ws out row 0..127
    const int wc = (tid & 1) * 8;     // ws k offset

    float acc[8][8];
#pragma unroll
    for (int i = 0; i < 8; i++)
#pragma unroll
        for (int j = 0; j < 8; j++) acc[i][j] = 0.f;

    for (int c0 = 0; c0 < C; c0 += 16) {
        float4 v0 = make_float4(0.f,0.f,0.f,0.f);
        float4 v1 = make_float4(0.f,0.f,0.f,0.f);
        if (nbase + ln < N_SRC) {
            const float4* xp =
                reinterpret_cast<const float4*>(&x[(size_t)(c0 + lc) * N_SRC + nbase + ln]);
            v0 = xp[0]; v1 = xp[1];
        }
        const float4* wp = reinterpret_cast<const float4*>(&W[(size_t)wo * C + c0 + wc]);
        const float4 w0 = wp[0], w1 = wp[1];

        __syncthreads();
        *reinterpret_cast<float4*>(&xs[lc][ln])     = v0;
        *reinterpret_cast<float4*>(&xs[lc][ln + 4]) = v1;
        ws[wc + 0][wo] = w0.x; ws[wc + 1][wo] = w0.y;
        ws[wc + 2][wo] = w0.z; ws[wc + 3][wo] = w0.w;
        ws[wc + 4][wo] = w1.x; ws[wc + 5][wo] = w1.y;
        ws[wc + 6][wo] = w1.z; ws[wc + 7][wo] = w1.w;
        __syncthreads();

#pragma unroll
        for (int kk = 0; kk < 16; kk++) {
            float an[8], ao[8];
            *reinterpret_cast<float4*>(&an[0]) = *reinterpret_cast<const float4*>(&xs[kk][tn * 8]);
            *reinterpret_cast<float4*>(&an[4]) = *reinterpret_cast<const float4*>(&xs[kk][tn * 8 + 4]);
            *reinterpret_cast<float4*>(&ao[0]) = *reinterpret_cast<const float4*>(&ws[kk][to * 8]);
            *reinterpret_cast<float4*>(&ao[4]) = *reinterpret_cast<const float4*>(&ws[kk][to * 8 + 4]);
#pragma unroll
            for (int i = 0; i < 8; i++)
#pragma unroll
                for (int j = 0; j < 8; j++)
                    acc[i][j] = fmaf(an[i], ao[j], acc[i][j]);
        }
    }

    float part[8];
#pragma unroll
    for (int i = 0; i < 8; i++) part[i] = 0.f;

#pragma unroll
    for (int j = 0; j < 8; j++) {
        const float bj = bs[to * 8 + j];
        const float aj = ats[to * 8 + j];
#pragma unroll
        for (int i = 0; i < 8; i++) {
            const float v = acc[i][j] + bj;
            acc[i][j] = v;
            part[i] = fmaf(v, aj, part[i]);
        }
    }

#pragma unroll
    for (int i = 0; i < 8; i++) {
        const int n = nbase + tn * 8 + i;
        if (n < N_SRC) {
            float* dst = &g_Wx[(size_t)n * C + to * 8];
            *reinterpret_cast<float4*>(dst) =
                make_float4(acc[i][0], acc[i][1], acc[i][2], acc[i][3]);
            *reinterpret_cast<float4*>(dst + 4) =
                make_float4(acc[i][4], acc[i][5], acc[i][6], acc[i][7]);
        }
    }

#pragma unroll
    for (int i = 0; i < 8; i++)
        atomicAdd(&sdot[tn * 8 + i], part[i]);
    __syncthreads();

    if (tid < 128) {
        const int n = nbase + tid;
        if (n < N_SRC) {
            float a = sdot[tid];
            const float alpha = *alphap;
            a = (a >= 0.f) ? a : alpha * a;
            g_expa[n] = __expf(a);
        }
    }
}

// ---------------- kernel 6: gather-accumulate + normalize + transposed write -
// Block = 256 threads (8 warps), covers 32 consecutive targets (4 per warp).
__global__ __launch_bounds__(256) void gather_kernel(float* __restrict__ out)
{
    __shared__ float tile[32][129];   // tile[c][o], pad for conflict-free read

    const int tid  = threadIdx.x;
    const int w    = tid >> 5;        // warp 0..7
    const int lane = tid & 31;
    const int n0   = blockIdx.x * 32;

#pragma unroll
    for (int r = 0; r < 4; r++) {
        const int c = w * 4 + r;          // target slot in block
        const int n = n0 + c;             // global target

        float4 acc = make_float4(0.f, 0.f, 0.f, 0.f);
        float  den = 0.f;

        const int beg = g_off[n];
        const int end = g_off[n + 1];

        for (int base = beg; base < end; base += 32) {
            const int m = end - base < 32 ? end - base : 32;
            int   src = 0;
            float ex  = 0.f;
            if (lane < m) {
                src = g_srcs[base + lane];
                ex  = g_expa[src];
            }
#pragma unroll 4
            for (int j = 0; j < m; j++) {
                const int   s = __shfl_sync(0xFFFFFFFFu, src, j);
                const float e = __shfl_sync(0xFFFFFFFFu, ex,  j);
                const float4 v =
                    *reinterpret_cast<const float4*>(&g_Wx[(size_t)s * C + lane * 4]);
                acc.x = fmaf(e, v.x, acc.x);
                acc.y = fmaf(e, v.y, acc.y);
                acc.z = fmaf(e, v.z, acc.z);
                acc.w = fmaf(e, v.w, acc.w);
                den += e;
            }
        }

        const float rd = 1.f / ((den == 0.f) ? 1.f : den);
        tile[c][lane * 4 + 0] = acc.x * rd;
        tile[c][lane * 4 + 1] = acc.y * rd;
        tile[c][lane * 4 + 2] = acc.z * rd;
        tile[c][lane * 4 + 3] = acc.w * rd;
    }
    __syncthreads();

    // coalesced transposed write: out[o][n0 + c]
    const int c = tid & 31;
#pragma unroll
    for (int r = 0; r < 16; r++) {
        const int o = (tid >> 5) + r * 8;
        out[(size_t)o * N_OUT + n0 + c] = tile[c][o];
    }
}

// ---------------- launch ------------------------------------------------------
extern "C" void kernel_launch(void* const* d_in, const int* in_sizes, int n_in,
                              void* d_out, int out_size)
{
    const float* x     = (const float*)d_in[0];
    const int*   edges = (const int*)  d_in[1];
    const float* W     = (const float*)d_in[2];
    const float* b     = (const float*)d_in[3];
    const float* att   = (const float*)d_in[4];
    const float* alpha = (const float*)d_in[5];
    float* out = (float*)d_out;

    zero_cnt_kernel<<<(N_OUT + 255) / 256, 256>>>();
    hist_kernel<<<1184, 256>>>(edges);
    scan_kernel<<<1, 1024>>>();
    reorder_kernel<<<1184, 256>>>(edges);
    gemm_kernel<<<(N_SRC + 127) / 128, 256>>>(x, W, b, att, alpha);
    gather_kernel<<<N_OUT / 32, 256>>>(out);
}

// round 3
// speedup vs baseline: 1.1119x; 1.1119x over previous
#include <cuda_runtime.h>
#include <cstdint>
#include <cstddef>

#define N_SRC   100000
#define N_OUT   100000
#define N_EDGES 1600000
#define C       128

typedef unsigned long long u64;

// ---------------- scratch (device globals; no allocation allowed) ------------
__device__ float g_Wx[(size_t)N_SRC * C];    // node-major: Wx[n][o], 51.2 MB
__device__ float g_num[(size_t)N_OUT * C];   // node-major accumulators, 51.2 MB
__device__ float g_expa[N_SRC];
__device__ float g_den[N_OUT];

// ---------------- kernel 1: zero the accumulators ----------------------------
__global__ void zero_kernel()
{
    size_t i      = (size_t)blockIdx.x * blockDim.x + threadIdx.x;
    size_t stride = (size_t)gridDim.x * blockDim.x;
    float4* np = reinterpret_cast<float4*>(g_num);
    const size_t n4 = (size_t)N_OUT * C / 4;
    for (size_t k = i; k < n4; k += stride)
        np[k] = make_float4(0.f, 0.f, 0.f, 0.f);
    for (size_t k = i; k < N_OUT; k += stride)
        g_den[k] = 0.f;
}

// ---------------- kernel 2: Wx = W @ x + b, fused score epilogue -------------
// Block tile: 128 nodes x 128 outs, BK=16, 256 threads, 8x8 micro-tile each.
// Inner product uses packed fma.rn.f32x2 (FFMA2) pairing the out-channel axis:
// 32 FFMA2 issues per k-step instead of 64 FFMA -> ~2x issue throughput.
__global__ __launch_bounds__(256) void gemm_kernel(
    const float* __restrict__ x,      // (C, N_SRC)
    const float* __restrict__ W,      // (C_OUT, C_IN) row-major
    const float* __restrict__ b,      // (C,)
    const float* __restrict__ att,    // (C,)
    const float* __restrict__ alphap) // scalar
{
    __shared__ float xs[16][132];   // xs[k][n]
    __shared__ float ws[16][132];   // ws[k][o]
    __shared__ float bs[128];
    __shared__ float ats[128];
    __shared__ float sdot[128];

    const int tid   = threadIdx.x;
    const int nbase = blockIdx.x * 128;

    if (tid < 128) {
        bs[tid]   = b[tid];
        ats[tid]  = att[tid];
        sdot[tid] = 0.f;
    }

    const int tn = tid >> 4;        // 0..15 node group
    const int to = tid & 15;        // 0..15 out group

    const int lc = tid >> 4;          // xs row (k) 0..15
    const int ln = (tid & 15) * 8;    // xs col (n)
    const int wo = tid >> 1;          // ws out row 0..127
    const int wc = (tid & 1) * 8;     // ws k offset

    // packed accumulators: acc2[i][j2] holds (acc[i][2*j2], acc[i][2*j2+1])
    u64 acc2[8][4];
#pragma unroll
    for (int i = 0; i < 8; i++)
#pragma unroll
        for (int j = 0; j < 4; j++) acc2[i][j] = 0ULL;

    for (int c0 = 0; c0 < C; c0 += 16) {
        float4 v0 = make_float4(0.f,0.f,0.f,0.f);
        float4 v1 = make_float4(0.f,0.f,0.f,0.f);
        if (nbase + ln < N_SRC) {
            const float4* xp =
                reinterpret_cast<const float4*>(&x[(size_t)(c0 + lc) * N_SRC + nbase + ln]);
            v0 = xp[0]; v1 = xp[1];
        }
        const float4* wp = reinterpret_cast<const float4*>(&W[(size_t)wo * C + c0 + wc]);
        const float4 w0 = wp[0], w1 = wp[1];

        __syncthreads();
        *reinterpret_cast<float4*>(&xs[lc][ln])     = v0;
        *reinterpret_cast<float4*>(&xs[lc][ln + 4]) = v1;
        ws[wc + 0][wo] = w0.x; ws[wc + 1][wo] = w0.y;
        ws[wc + 2][wo] = w0.z; ws[wc + 3][wo] = w0.w;
        ws[wc + 4][wo] = w1.x; ws[wc + 5][wo] = w1.y;
        ws[wc + 6][wo] = w1.z; ws[wc + 7][wo] = w1.w;
        __syncthreads();

#pragma unroll
        for (int kk = 0; kk < 16; kk++) {
            float an[8];
            *reinterpret_cast<float4*>(&an[0]) = *reinterpret_cast<const float4*>(&xs[kk][tn * 8]);
            *reinterpret_cast<float4*>(&an[4]) = *reinterpret_cast<const float4*>(&xs[kk][tn * 8 + 4]);

            union { float4 f4; u64 u2[2]; } AO0, AO1;
            AO0.f4 = *reinterpret_cast<const float4*>(&ws[kk][to * 8]);
            AO1.f4 = *reinterpret_cast<const float4*>(&ws[kk][to * 8 + 4]);
            u64 ao2[4];
            ao2[0] = AO0.u2[0]; ao2[1] = AO0.u2[1];
            ao2[2] = AO1.u2[0]; ao2[3] = AO1.u2[1];

#pragma unroll
            for (int i = 0; i < 8; i++) {
                u64 an2;
                asm("mov.b64 %0, {%1, %1};" : "=l"(an2) : "f"(an[i]));
#pragma unroll
                for (int j = 0; j < 4; j++)
                    asm("fma.rn.f32x2 %0, %1, %2, %0;"
                        : "+l"(acc2[i][j]) : "l"(an2), "l"(ao2[j]));
            }
        }
    }

    // ---- epilogue: unpack, bias, partial attention dot, Wx store ----
    float acc[8][8];
#pragma unroll
    for (int i = 0; i < 8; i++)
#pragma unroll
        for (int j = 0; j < 4; j++) {
            union { u64 u; float2 f2; } cv;
            cv.u = acc2[i][j];
            acc[i][2 * j]     = cv.f2.x;
            acc[i][2 * j + 1] = cv.f2.y;
        }

    float part[8];
#pragma unroll
    for (int i = 0; i < 8; i++) part[i] = 0.f;

#pragma unroll
    for (int j = 0; j < 8; j++) {
        const float bj = bs[to * 8 + j];
        const float aj = ats[to * 8 + j];
#pragma unroll
        for (int i = 0; i < 8; i++) {
            const float v = acc[i][j] + bj;
            acc[i][j] = v;
            part[i] = fmaf(v, aj, part[i]);
        }
    }

#pragma unroll
    for (int i = 0; i < 8; i++) {
        const int n = nbase + tn * 8 + i;
        if (n < N_SRC) {
            float* dst = &g_Wx[(size_t)n * C + to * 8];
            *reinterpret_cast<float4*>(dst) =
                make_float4(acc[i][0], acc[i][1], acc[i][2], acc[i][3]);
            *reinterpret_cast<float4*>(dst + 4) =
                make_float4(acc[i][4], acc[i][5], acc[i][6], acc[i][7]);
        }
    }

#pragma unroll
    for (int i = 0; i < 8; i++)
        atomicAdd(&sdot[tn * 8 + i], part[i]);
    __syncthreads();

    if (tid < 128) {
        const int n = nbase + tid;
        if (n < N_SRC) {
            float a = sdot[tid];
            const float alpha = *alphap;
            a = (a >= 0.f) ? a : alpha * a;
            g_expa[n] = __expf(a);
        }
    }
}

// ---------------- kernel 3: edge scatter (1 warp per edge) -------------------
__global__ __launch_bounds__(256) void scatter_kernel(const int* __restrict__ edges)
{
    const int e    = blockIdx.x * 8 + (threadIdx.x >> 5);
    const int lane = threadIdx.x & 31;

    const int2 ts = reinterpret_cast<const int2*>(edges)[e];
    const int tgt = ts.x;
    const int src = ts.y;

    const float ex = __ldg((const float*)&g_expa[src]);

    float4 v = *reinterpret_cast<const float4*>(&g_Wx[(size_t)src * C + lane * 4]);
    v.x *= ex; v.y *= ex; v.z *= ex; v.w *= ex;

    float* np = &g_num[(size_t)tgt * C + lane * 4];
    asm volatile("red.global.add.v4.f32 [%0], {%1, %2, %3, %4};"
                 :: "l"(np), "f"(v.x), "f"(v.y), "f"(v.z), "f"(v.w)
                 : "memory");

    if (lane == 0)
        atomicAdd(&g_den[tgt], ex);
}

// ---------------- kernel 4: normalize + transpose to (C, N_OUT) --------------
__global__ __launch_bounds__(256) void finalize_kernel(float* __restrict__ out)
{
    __shared__ float tile[32][33];
    __shared__ float dsh[32];

    const int tx = threadIdx.x;       // 0..31
    const int ty = threadIdx.y;       // 0..7
    const int n0 = blockIdx.x * 32;
    const int o0 = blockIdx.y * 32;

    if (ty == 0) {
        const int n = n0 + tx;
        float d = (n < N_OUT) ? g_den[n] : 1.f;
        dsh[tx] = (d == 0.f) ? 1.f : d;
    }

#pragma unroll
    for (int r = 0; r < 4; r++) {
        const int n = n0 + ty + r * 8;
        if (n < N_OUT)
            tile[ty + r * 8][tx] = g_num[(size_t)n * C + o0 + tx];
    }
    __syncthreads();

    const float rd = 1.f / dsh[tx];
#pragma unroll
    for (int r = 0; r < 4; r++) {
        const int o = o0 + ty + r * 8;
        const int n = n0 + tx;
        if (n < N_OUT)
            out[(size_t)o * N_OUT + n] = tile[tx][ty + r * 8] * rd;
    }
}

// ---------------- launch ------------------------------------------------------
extern "C" void kernel_launch(void* const* d_in, const int* in_sizes, int n_in,
                              void* d_out, int out_size)
{
    const float* x     = (const float*)d_in[0];
    const int*   edges = (const int*)  d_in[1];
    const float* W     = (const float*)d_in[2];
    const float* b     = (const float*)d_in[3];
    const float* att   = (const float*)d_in[4];
    const float* alpha = (const float*)d_in[5];
    float* out = (float*)d_out;

    zero_kernel<<<2048, 256>>>();
    gemm_kernel<<<(N_SRC + 127) / 128, 256>>>(x, W, b, att, alpha);
    scatter_kernel<<<N_EDGES / 8, 256>>>(edges);
    dim3 fgrid((N_OUT + 31) / 32, C / 32);
    finalize_kernel<<<fgrid, dim3(32, 8)>>>(out);
}

// round 4
// speedup vs baseline: 1.2161x; 1.0937x over previous
#include <cuda_runtime.h>
#include <cuda_fp16.h>
#include <cstdint>
#include <cstddef>

#define N_SRC   100000
#define N_OUT   100000
#define N_EDGES 1600000
#define C       128

// ---------------- scratch (device globals; no allocation allowed) ------------
__device__ __half g_Wxh[(size_t)N_SRC * C];  // node-major fp16 Wx, 25.6 MB
__device__ float  g_num[(size_t)N_OUT * C];  // node-major accumulators, 51.2 MB
__device__ float  g_expa[N_SRC];
__device__ float  g_den[N_OUT];

// ---------------- kernel 1: zero the accumulators ----------------------------
__global__ void zero_kernel()
{
    size_t i      = (size_t)blockIdx.x * blockDim.x + threadIdx.x;
    size_t stride = (size_t)gridDim.x * blockDim.x;
    float4* np = reinterpret_cast<float4*>(g_num);
    const size_t n4 = (size_t)N_OUT * C / 4;
    for (size_t k = i; k < n4; k += stride)
        np[k] = make_float4(0.f, 0.f, 0.f, 0.f);
    for (size_t k = i; k < N_OUT; k += stride)
        g_den[k] = 0.f;
}

// ---------------- kernel 2: Wx = W @ x + b, fused score epilogue -------------
// Block tile: 128 nodes x 128 outs, BK=16, 256 threads, 8x8 micro-tile each.
// Scores (a, expa) computed from exact fp32 accumulators; Wx stored fp16.
__global__ __launch_bounds__(256) void gemm_kernel(
    const float* __restrict__ x,      // (C, N_SRC)
    const float* __restrict__ W,      // (C_OUT, C_IN) row-major
    const float* __restrict__ b,      // (C,)
    const float* __restrict__ att,    // (C,)
    const float* __restrict__ alphap) // scalar
{
    __shared__ float xs[16][132];   // xs[k][n]
    __shared__ float ws[16][132];   // ws[k][o]
    __shared__ float bs[128];
    __shared__ float ats[128];
    __shared__ float sdot[128];

    const int tid   = threadIdx.x;
    const int nbase = blockIdx.x * 128;

    if (tid < 128) {
        bs[tid]   = b[tid];
        ats[tid]  = att[tid];
        sdot[tid] = 0.f;
    }

    const int tn = tid >> 4;        // 0..15 node group
    const int to = tid & 15;        // 0..15 out group

    const int lc = tid >> 4;          // xs row (k) 0..15
    const int ln = (tid & 15) * 8;    // xs col (n)
    const int wo = tid >> 1;          // ws out row 0..127
    const int wc = (tid & 1) * 8;     // ws k offset

    float acc[8][8];
#pragma unroll
    for (int i = 0; i < 8; i++)
#pragma unroll
        for (int j = 0; j < 8; j++) acc[i][j] = 0.f;

    for (int c0 = 0; c0 < C; c0 += 16) {
        float4 v0 = make_float4(0.f,0.f,0.f,0.f);
        float4 v1 = make_float4(0.f,0.f,0.f,0.f);
        if (nbase + ln < N_SRC) {
            const float4* xp =
                reinterpret_cast<const float4*>(&x[(size_t)(c0 + lc) * N_SRC + nbase + ln]);
            v0 = xp[0]; v1 = xp[1];
        }
        const float4* wp = reinterpret_cast<const float4*>(&W[(size_t)wo * C + c0 + wc]);
        const float4 w0 = wp[0], w1 = wp[1];

        __syncthreads();
        *reinterpret_cast<float4*>(&xs[lc][ln])     = v0;
        *reinterpret_cast<float4*>(&xs[lc][ln + 4]) = v1;
        ws[wc + 0][wo] = w0.x; ws[wc + 1][wo] = w0.y;
        ws[wc + 2][wo] = w0.z; ws[wc + 3][wo] = w0.w;
        ws[wc + 4][wo] = w1.x; ws[wc + 5][wo] = w1.y;
        ws[wc + 6][wo] = w1.z; ws[wc + 7][wo] = w1.w;
        __syncthreads();

#pragma unroll
        for (int kk = 0; kk < 16; kk++) {
            float an[8], ao[8];
            *reinterpret_cast<float4*>(&an[0]) = *reinterpret_cast<const float4*>(&xs[kk][tn * 8]);
            *reinterpret_cast<float4*>(&an[4]) = *reinterpret_cast<const float4*>(&xs[kk][tn * 8 + 4]);
            *reinterpret_cast<float4*>(&ao[0]) = *reinterpret_cast<const float4*>(&ws[kk][to * 8]);
            *reinterpret_cast<float4*>(&ao[4]) = *reinterpret_cast<const float4*>(&ws[kk][to * 8 + 4]);
#pragma unroll
            for (int i = 0; i < 8; i++)
#pragma unroll
                for (int j = 0; j < 8; j++)
                    acc[i][j] = fmaf(an[i], ao[j], acc[i][j]);
        }
    }

    // ---- epilogue: bias, exact fp32 attention dot, fp16 Wx store ----
    float part[8];
#pragma unroll
    for (int i = 0; i < 8; i++) part[i] = 0.f;

#pragma unroll
    for (int j = 0; j < 8; j++) {
        const float bj = bs[to * 8 + j];
        const float aj = ats[to * 8 + j];
#pragma unroll
        for (int i = 0; i < 8; i++) {
            const float v = acc[i][j] + bj;
            acc[i][j] = v;
            part[i] = fmaf(v, aj, part[i]);
        }
    }

#pragma unroll
    for (int i = 0; i < 8; i++) {
        const int n = nbase + tn * 8 + i;
        if (n < N_SRC) {
            __half2 h0 = __floats2half2_rn(acc[i][0], acc[i][1]);
            __half2 h1 = __floats2half2_rn(acc[i][2], acc[i][3]);
            __half2 h2 = __floats2half2_rn(acc[i][4], acc[i][5]);
            __half2 h3 = __floats2half2_rn(acc[i][6], acc[i][7]);
            uint4 pk;
            pk.x = *reinterpret_cast<unsigned*>(&h0);
            pk.y = *reinterpret_cast<unsigned*>(&h1);
            pk.z = *reinterpret_cast<unsigned*>(&h2);
            pk.w = *reinterpret_cast<unsigned*>(&h3);
            *reinterpret_cast<uint4*>(&g_Wxh[(size_t)n * C + to * 8]) = pk;
        }
    }

    // reduce attention dot across the 16 out-groups (exact fp32)
#pragma unroll
    for (int i = 0; i < 8; i++)
        atomicAdd(&sdot[tn * 8 + i], part[i]);
    __syncthreads();

    if (tid < 128) {
        const int n = nbase + tid;
        if (n < N_SRC) {
            float a = sdot[tid];
            const float alpha = *alphap;
            a = (a >= 0.f) ? a : alpha * a;
            g_expa[n] = __expf(a);
        }
    }
}

// ---------------- kernel 3: edge scatter (1 warp per edge, fp16 gather) ------
__global__ __launch_bounds__(256) void scatter_kernel(const int* __restrict__ edges)
{
    const int e    = blockIdx.x * 8 + (threadIdx.x >> 5);
    const int lane = threadIdx.x & 31;

    const int2 ts = reinterpret_cast<const int2*>(edges)[e];
    const int tgt = ts.x;
    const int src = ts.y;

    const float ex = __ldg((const float*)&g_expa[src]);

    // each lane covers 4 channels: 8 bytes of fp16 (row = 256B, fully coalesced)
    const uint2 h = *reinterpret_cast<const uint2*>(&g_Wxh[(size_t)src * C + lane * 4]);
    const float2 f0 = __half22float2(*reinterpret_cast<const __half2*>(&h.x));
    const float2 f1 = __half22float2(*reinterpret_cast<const __half2*>(&h.y));

    float4 v;
    v.x = f0.x * ex; v.y = f0.y * ex;
    v.z = f1.x * ex; v.w = f1.y * ex;

    float* np = &g_num[(size_t)tgt * C + lane * 4];
    asm volatile("red.global.add.v4.f32 [%0], {%1, %2, %3, %4};"
                 :: "l"(np), "f"(v.x), "f"(v.y), "f"(v.z), "f"(v.w)
                 : "memory");

    if (lane == 0)
        atomicAdd(&g_den[tgt], ex);
}

// ---------------- kernel 4: normalize + transpose to (C, N_OUT) --------------
__global__ __launch_bounds__(256) void finalize_kernel(float* __restrict__ out)
{
    __shared__ float tile[32][33];
    __shared__ float dsh[32];

    const int tx = threadIdx.x;       // 0..31
    const int ty = threadIdx.y;       // 0..7
    const int n0 = blockIdx.x * 32;
    const int o0 = blockIdx.y * 32;

    if (ty == 0) {
        const int n = n0 + tx;
        float d = (n < N_OUT) ? g_den[n] : 1.f;
        dsh[tx] = (d == 0.f) ? 1.f : d;
    }

#pragma unroll
    for (int r = 0; r < 4; r++) {
        const int n = n0 + ty + r * 8;
        if (n < N_OUT)
            tile[ty + r * 8][tx] = g_num[(size_t)n * C + o0 + tx];
    }
    __syncthreads();

    const float rd = 1.f / dsh[tx];
#pragma unroll
    for (int r = 0; r < 4; r++) {
        const int o = o0 + ty + r * 8;
        const int n = n0 + tx;
        if (n < N_OUT)
            out[(size_t)o * N_OUT + n] = tile[tx][ty + r * 8] * rd;
    }
}

// ---------------- launch ------------------------------------------------------
extern "C" void kernel_launch(void* const* d_in, const int* in_sizes, int n_in,
                              void* d_out, int out_size)
{
    const float* x     = (const float*)d_in[0];
    const int*   edges = (const int*)  d_in[1];
    const float* W     = (const float*)d_in[2];
    const float* b     = (const float*)d_in[3];
    const float* att   = (const float*)d_in[4];
    const float* alpha = (const float*)d_in[5];
    float* out = (float*)d_out;

    zero_kernel<<<2048, 256>>>();
    gemm_kernel<<<(N_SRC + 127) / 128, 256>>>(x, W, b, att, alpha);
    scatter_kernel<<<N_EDGES / 8, 256>>>(edges);
    dim3 fgrid((N_OUT + 31) / 32, C / 32);
    finalize_kernel<<<fgrid, dim3(32, 8)>>>(out);
}

// round 5
// speedup vs baseline: 1.4981x; 1.2319x over previous
#include <cuda_runtime.h>
#include <cuda_fp16.h>
#include <cuda_bf16.h>
#include <cstdint>
#include <cstddef>

#define N_SRC   100000
#define N_OUT   100000
#define N_EDGES 1600000
#define C       128

// ---------------- scratch (device globals; no allocation allowed) ------------
__device__ __half g_Wxh[(size_t)N_SRC * C];  // node-major fp16 Wx, 25.6 MB
__device__ float  g_num[(size_t)N_OUT * C];  // node-major accumulators, 51.2 MB
__device__ float  g_expa[N_SRC];
__device__ float  g_den[N_OUT];

// ---------------- kernel 1: zero the accumulators ----------------------------
__global__ void zero_kernel()
{
    size_t i      = (size_t)blockIdx.x * blockDim.x + threadIdx.x;
    size_t stride = (size_t)gridDim.x * blockDim.x;
    float4* np = reinterpret_cast<float4*>(g_num);
    const size_t n4 = (size_t)N_OUT * C / 4;
    for (size_t k = i; k < n4; k += stride)
        np[k] = make_float4(0.f, 0.f, 0.f, 0.f);
    for (size_t k = i; k < N_OUT; k += stride)
        g_den[k] = 0.f;
}

// ---------------- tensor-core GEMM helpers -----------------------------------
#define LDSM_X4(r0, r1, r2, r3, addr)                                          \
    asm volatile("ldmatrix.sync.aligned.m8n8.x4.shared.b16 {%0,%1,%2,%3},[%4];"\
                 : "=r"(r0), "=r"(r1), "=r"(r2), "=r"(r3) : "r"(addr))

#define LDSM_X4_T(r0, r1, r2, r3, addr)                                        \
    asm volatile("ldmatrix.sync.aligned.m8n8.x4.trans.shared.b16 {%0,%1,%2,%3},[%4];"\
                 : "=r"(r0), "=r"(r1), "=r"(r2), "=r"(r3) : "r"(addr))

#define MMA_BF16(c, a0, a1, a2, a3, b0, b1)                                    \
    asm volatile("mma.sync.aligned.m16n8k16.row.col.f32.bf16.bf16.f32 "        \
                 "{%0,%1,%2,%3},{%4,%5,%6,%7},{%8,%9},{%0,%1,%2,%3};"          \
                 : "+f"(c[0]), "+f"(c[1]), "+f"(c[2]), "+f"(c[3])              \
                 : "r"(a0), "r"(a1), "r"(a2), "r"(a3), "r"(b0), "r"(b1))

__device__ __forceinline__ void cvt_hilo4(float4 v, unsigned& hi0, unsigned& hi1,
                                          unsigned& lo0, unsigned& lo1)
{
    float f[4] = {v.x, v.y, v.z, v.w};
    unsigned short h[4], l[4];
#pragma unroll
    for (int i = 0; i < 4; i++) {
        __nv_bfloat16 hb = __float2bfloat16(f[i]);
        __nv_bfloat16 lb = __float2bfloat16(f[i] - __bfloat162float(hb));
        h[i] = __bfloat16_as_ushort(hb);
        l[i] = __bfloat16_as_ushort(lb);
    }
    hi0 = ((unsigned)h[1] << 16) | h[0];
    hi1 = ((unsigned)h[3] << 16) | h[2];
    lo0 = ((unsigned)l[1] << 16) | l[0];
    lo1 = ((unsigned)l[3] << 16) | l[2];
}

// ---------------- kernel 2: Wx = W @ x + b via bf16-split mma.sync -----------
// Block: 128 nodes (n) x 128 outs (o). 256 threads / 8 warps.
// Warp w owns n in [w*16, w*16+16), all 128 o. K staged in 4 chunks of 32.
// A = W (row-major, k contig, ldmatrix.x4); B = x tile Bs[k][n] (ldmatrix.x4.trans).
// D += Whi*xhi + Whi*xlo + Wlo*xhi  (fp32 accum; ~1e-5 relative error).
#define A_PITCH 40    // 32 k + 8 pad (bf16)
#define B_PITCH 136   // 128 n + 8 pad (bf16)

__global__ __launch_bounds__(256, 2) void gemm_kernel(
    const float* __restrict__ x,      // (C, N_SRC)
    const float* __restrict__ W,      // (C_OUT, C_IN) row-major
    const float* __restrict__ b,      // (C,)
    const float* __restrict__ att,    // (C,)
    const float* __restrict__ alphap) // scalar
{
    __shared__ __align__(16) unsigned char sbuf[37888];
    __nv_bfloat16* As_hi = reinterpret_cast<__nv_bfloat16*>(sbuf);          // [128][40]
    __nv_bfloat16* As_lo = reinterpret_cast<__nv_bfloat16*>(sbuf + 10240);
    __nv_bfloat16* Bs_hi = reinterpret_cast<__nv_bfloat16*>(sbuf + 20480);  // [32][136]
    __nv_bfloat16* Bs_lo = reinterpret_cast<__nv_bfloat16*>(sbuf + 29184);
    __half*        S     = reinterpret_cast<__half*>(sbuf);                 // epilogue [128][136]
    __shared__ float bsh[128], ash[128];

    const int tid  = threadIdx.x;
    const int w    = tid >> 5;
    const int lane = tid & 31;
    const int nbase = blockIdx.x * 128;

    if (tid < 128) { bsh[tid] = b[tid]; ash[tid] = att[tid]; }
    const float alpha = __ldg(alphap);

    const unsigned saAhi = (unsigned)__cvta_generic_to_shared(As_hi);
    const unsigned saAlo = (unsigned)__cvta_generic_to_shared(As_lo);
    const unsigned saBhi = (unsigned)__cvta_generic_to_shared(Bs_hi);
    const unsigned saBlo = (unsigned)__cvta_generic_to_shared(Bs_lo);

    const int lrow  = lane & 15;         // ldmatrix row within 16
    const int lcol8 = (lane >> 4) * 8;   // 0 or 8

    float cc[8][2][4];
#pragma unroll
    for (int mt = 0; mt < 8; mt++)
#pragma unroll
        for (int nt = 0; nt < 2; nt++)
#pragma unroll
            for (int j = 0; j < 4; j++) cc[mt][nt][j] = 0.f;

    const int wn = w * 16;

    for (int kc = 0; kc < 4; kc++) {
        const int kbase = kc * 32;
        __syncthreads();   // previous chunk fully consumed

        // ---- load W chunk -> As (128 o x 32 k) ----
#pragma unroll
        for (int it = 0; it < 4; it++) {
            const int idx = it * 256 + tid;       // 0..1023 float4s
            const int o   = idx >> 3;
            const int kq  = (idx & 7) * 4;
            float4 v = *reinterpret_cast<const float4*>(&W[(size_t)o * C + kbase + kq]);
            unsigned h0, h1, l0, l1;
            cvt_hilo4(v, h0, h1, l0, l1);
            unsigned* dh = reinterpret_cast<unsigned*>(&As_hi[o * A_PITCH + kq]);
            unsigned* dl = reinterpret_cast<unsigned*>(&As_lo[o * A_PITCH + kq]);
            dh[0] = h0; dh[1] = h1;
            dl[0] = l0; dl[1] = l1;
        }

        // ---- load x chunk -> Bs (32 k x 128 n), natural layout ----
#pragma unroll
        for (int it = 0; it < 4; it++) {
            const int r = it * 8 + w;             // k row 0..31
            const int n = nbase + lane * 4;
            float4 v = make_float4(0.f, 0.f, 0.f, 0.f);
            if (n < N_SRC)
                v = *reinterpret_cast<const float4*>(&x[(size_t)(kbase + r) * N_SRC + n]);
            unsigned h0, h1, l0, l1;
            cvt_hilo4(v, h0, h1, l0, l1);
            unsigned* dh = reinterpret_cast<unsigned*>(&Bs_hi[r * B_PITCH + lane * 4]);
            unsigned* dl = reinterpret_cast<unsigned*>(&Bs_lo[r * B_PITCH + lane * 4]);
            dh[0] = h0; dh[1] = h1;
            dl[0] = l0; dl[1] = l1;
        }
        __syncthreads();

        // ---- compute: 2 k-steps of 16 within this chunk ----
#pragma unroll
        for (int ks = 0; ks < 2; ks++) {
            const int ko = ks * 16;
            const unsigned boff = (unsigned)(((ko + lrow) * B_PITCH + wn + lcol8) * 2);
            unsigned bh0, bh1, bh2, bh3, bl0, bl1, bl2, bl3;
            LDSM_X4_T(bh0, bh1, bh2, bh3, saBhi + boff);
            LDSM_X4_T(bl0, bl1, bl2, bl3, saBlo + boff);

#pragma unroll
            for (int mt = 0; mt < 8; mt++) {
                const unsigned aoff =
                    (unsigned)(((mt * 16 + lrow) * A_PITCH + ko + lcol8) * 2);
                unsigned ah0, ah1, ah2, ah3, al0, al1, al2, al3;
                LDSM_X4(ah0, ah1, ah2, ah3, saAhi + aoff);
                LDSM_X4(al0, al1, al2, al3, saAlo + aoff);

                MMA_BF16(cc[mt][0], ah0, ah1, ah2, ah3, bh0, bh1);
                MMA_BF16(cc[mt][1], ah0, ah1, ah2, ah3, bh2, bh3);
                MMA_BF16(cc[mt][0], ah0, ah1, ah2, ah3, bl0, bl1);
                MMA_BF16(cc[mt][1], ah0, ah1, ah2, ah3, bl2, bl3);
                MMA_BF16(cc[mt][0], al0, al1, al2, al3, bh0, bh1);
                MMA_BF16(cc[mt][1], al0, al1, al2, al3, bh2, bh3);
            }
        }
    }

    __syncthreads();   // mainloop smem dead; S may now alias it

    // ---- epilogue: bias, att-dot, fp16 staging ----
    const int g  = lane >> 2;
    const int tg = lane & 3;
    float part[2][2] = {{0.f, 0.f}, {0.f, 0.f}};

#pragma unroll
    for (int mt = 0; mt < 8; mt++) {
        const int o0 = mt * 16 + g;
        const int o1 = o0 + 8;
        const float b0 = bsh[o0], b1 = bsh[o1];
        const float a0 = ash[o0], a1 = ash[o1];
#pragma unroll
        for (int nt = 0; nt < 2; nt++) {
            const float c0 = cc[mt][nt][0] + b0;
            const float c1 = cc[mt][nt][1] + b0;
            const float c2 = cc[mt][nt][2] + b1;
            const float c3 = cc[mt][nt][3] + b1;
            const int n0 = wn + nt * 8 + tg * 2;
            S[n0 * B_PITCH + o0]       = __float2half(c0);
            S[(n0 + 1) * B_PITCH + o0] = __float2half(c1);
            S[n0 * B_PITCH + o1]       = __float2half(c2);
            S[(n0 + 1) * B_PITCH + o1] = __float2half(c3);
            part[nt][0] += a0 * c0 + a1 * c2;
            part[nt][1] += a0 * c1 + a1 * c3;
        }
    }

    // reduce att-dot across the 8 g-groups (lanes stride 4)
#pragma unroll
    for (int m = 4; m < 32; m <<= 1)
#pragma unroll
        for (int nt = 0; nt < 2; nt++)
#pragma unroll
            for (int j = 0; j < 2; j++)
                part[nt][j] += __shfl_xor_sync(0xFFFFFFFFu, part[nt][j], m);

    if (lane < 4) {
#pragma unroll
        for (int nt = 0; nt < 2; nt++) {
#pragma unroll
            for (int j = 0; j < 2; j++) {
                const int n = nbase + wn + nt * 8 + lane * 2 + j;
                if (n < N_SRC) {
                    float a = part[nt][j];
                    a = (a >= 0.f) ? a : alpha * a;
                    g_expa[n] = __expf(a);
                }
            }
        }
    }
    __syncthreads();

    // ---- coalesced fp16 Wx store: 128 rows x 128 halves ----
    for (int idx = tid; idx < 128 * 16; idx += 256) {
        const int n  = idx >> 4;
        const int c8 = (idx & 15) * 8;
        const int gn = nbase + n;
        if (gn < N_SRC)
            *reinterpret_cast<uint4*>(&g_Wxh[(size_t)gn * C + c8]) =
                *reinterpret_cast<const uint4*>(&S[n * B_PITCH + c8]);
    }
}

// ---------------- kernel 3: edge scatter (1 warp per edge, fp16 gather) ------
__global__ __launch_bounds__(256) void scatter_kernel(const int* __restrict__ edges)
{
    const int e    = blockIdx.x * 8 + (threadIdx.x >> 5);
    const int lane = threadIdx.x & 31;

    const int2 ts = reinterpret_cast<const int2*>(edges)[e];
    const int tgt = ts.x;
    const int src = ts.y;

    const float ex = __ldg((const float*)&g_expa[src]);

    const uint2 h = *reinterpret_cast<const uint2*>(&g_Wxh[(size_t)src * C + lane * 4]);
    const float2 f0 = __half22float2(*reinterpret_cast<const __half2*>(&h.x));
    const float2 f1 = __half22float2(*reinterpret_cast<const __half2*>(&h.y));

    float4 v;
    v.x = f0.x * ex; v.y = f0.y * ex;
    v.z = f1.x * ex; v.w = f1.y * ex;

    float* np = &g_num[(size_t)tgt * C + lane * 4];
    asm volatile("red.global.add.v4.f32 [%0], {%1, %2, %3, %4};"
                 :: "l"(np), "f"(v.x), "f"(v.y), "f"(v.z), "f"(v.w)
                 : "memory");

    if (lane == 0)
        atomicAdd(&g_den[tgt], ex);
}

// ---------------- kernel 4: normalize + transpose to (C, N_OUT) --------------
__global__ __launch_bounds__(256) void finalize_kernel(float* __restrict__ out)
{
    __shared__ float tile[32][33];
    __shared__ float dsh[32];

    const int tx = threadIdx.x;       // 0..31
    const int ty = threadIdx.y;       // 0..7
    const int n0 = blockIdx.x * 32;
    const int o0 = blockIdx.y * 32;

    if (ty == 0) {
        const int n = n0 + tx;
        float d = (n < N_OUT) ? g_den[n] : 1.f;
        dsh[tx] = (d == 0.f) ? 1.f : d;
    }

#pragma unroll
    for (int r = 0; r < 4; r++) {
        const int n = n0 + ty + r * 8;
        if (n < N_OUT)
            tile[ty + r * 8][tx] = g_num[(size_t)n * C + o0 + tx];
    }
    __syncthreads();

    const float rd = 1.f / dsh[tx];
#pragma unroll
    for (int r = 0; r < 4; r++) {
        const int o = o0 + ty + r * 8;
        const int n = n0 + tx;
        if (n < N_OUT)
            out[(size_t)o * N_OUT + n] = tile[tx][ty + r * 8] * rd;
    }
}

// ---------------- launch ------------------------------------------------------
extern "C" void kernel_launch(void* const* d_in, const int* in_sizes, int n_in,
                              void* d_out, int out_size)
{
    const float* x     = (const float*)d_in[0];
    const int*   edges = (const int*)  d_in[1];
    const float* W     = (const float*)d_in[2];
    const float* b     = (const float*)d_in[3];
    const float* att   = (const float*)d_in[4];
    const float* alpha = (const float*)d_in[5];
    float* out = (float*)d_out;

    zero_kernel<<<2048, 256>>>();
    gemm_kernel<<<(N_SRC + 127) / 128, 256>>>(x, W, b, att, alpha);
    scatter_kernel<<<N_EDGES / 8, 256>>>(edges);
    dim3 fgrid((N_OUT + 31) / 32, C / 32);
    finalize_kernel<<<fgrid, dim3(32, 8)>>>(out);
}